// round 3
// baseline (speedup 1.0000x reference)
#include <cuda_runtime.h>
#include <math.h>
#include <stdint.h>

#define NPATH 11

// ---------------------------------------------------------------------------
// device globals (no allocation allowed)
// ---------------------------------------------------------------------------
__device__ float g_hctp_cg[NPATH * 125];            // compact [p][(m1*d2+m2)*d3+k]
__device__ float g_hctp_wT[(size_t)NPATH * 64 * 64 * 64];  // [p][i][j][o]

// ---------------------------------------------------------------------------
// CG builder (fp64, replicates numpy pipeline; l=2 basis analytic from LAPACK)
// ---------------------------------------------------------------------------
__device__ __forceinline__ double d_fact(int n){ double f=1; for(int i=2;i<=n;i++) f*=i; return f; }
__device__ __forceinline__ double d_dfact(int n){ double o=1; for(int k=n;k>0;k-=2) o*=k; return o; }
__device__ __forceinline__ double d_gmom(int n){ return (n&1) ? 0.0 : d_dfact(n-1); }
__device__ __forceinline__ int d_cidx(int L,int a,int b){ int t=L-a; return t*(t+1)/2 + (t-b); }

__device__ __forceinline__ double d_getB(int l, int i, int m, const double B2[6][5]){
    if (l==0) return 1.0;
    if (l==1) return (i==m) ? 1.0 : 0.0;
    return B2[i][m];
}

__global__ void hctp_build_cg(){
    __shared__ double sGL[NPATH][15][15];
    __shared__ double sV [NPATH][15][5];
    __shared__ double sR [NPATH][5][15];
    __shared__ double sG [NPATH][5][5];

    const int t = threadIdx.x;
    if (t >= NPATH) return;

    const int L1t[NPATH]={0,0,0,1,1,1,1,2,2,2,2};
    const int L2t[NPATH]={0,1,2,0,1,1,2,0,1,2,2};
    const int L3t[NPATH]={0,1,2,1,0,2,1,2,1,0,2};
    const int l1=L1t[t], l2=L2t[t], l3=L3t[t];
    const int L = l1 + l2;
    const int DL = (L+1)*(L+2)/2;
    const int d1 = 2*l1+1, d2 = 2*l2+1, d3 = 2*l3+1;

    // l=2 harmonic basis, gram-normalized (rows: x2,xy,xz,y2,yz,z2; cols m)
    double B2[6][5];
    for (int i=0;i<6;i++) for (int m=0;m<5;m++) B2[i][m]=0.0;
    {
        double s3 = sqrt(3.0), s2 = sqrt(2.0), s6 = sqrt(6.0);
        double pp = (3.0+s3)/(6.0*s2);
        double qq = (3.0-s3)/(6.0*s2);
        double rr = 1.0/s6;
        B2[1][0]=1.0;  B2[2][1]=1.0;  B2[4][3]=1.0;
        B2[0][2]=-rr;  B2[3][2]= pp;  B2[5][2]=-qq;
        B2[0][4]=-rr;  B2[3][4]=-qq;  B2[5][4]= pp;
    }

    // counts list for degree L
    int ca[15], cb[15];
    { int n=0; for(int a=L;a>=0;a--) for(int b=L-a;b>=0;b--){ ca[n]=a; cb[n]=b; n++; } }

    // Gaussian gram Sym^L
    for (int i=0;i<DL;i++) for (int j=0;j<DL;j++){
        int aa = ca[i]+ca[j], bb = cb[i]+cb[j];
        int cc = (L-ca[i]-cb[i]) + (L-ca[j]-cb[j]);
        sGL[t][i][j] = d_gmom(aa)*d_gmom(bb)*d_gmom(cc);
    }

    // V = r^{2k}-lift of harmonic basis of l3 into Sym^L    [DL x d3]
    const int kr = (L - l3)/2;
    const int Dl = (l3+1)*(l3+2)/2;
    int la[6], lb[6];
    { int n=0; for(int a=l3;a>=0;a--) for(int b=l3-a;b>=0;b--){ la[n]=a; lb[n]=b; n++; } }
    for (int i=0;i<DL;i++) for (int m=0;m<d3;m++) sV[t][i][m]=0.0;
    for (int j=0;j<Dl;j++){
        for (int p=0;p<=kr;p++) for (int q=0;q<=kr-p;q++){
            int r = kr - p - q;
            double coef = d_fact(kr)/(d_fact(p)*d_fact(q)*d_fact(r));
            int row = d_cidx(L, la[j]+2*p, lb[j]+2*q);
            for (int m=0;m<d3;m++) sV[t][row][m] += coef * d_getB(l3, j, m, B2);
        }
    }

    // R = V^T GL  [d3 x DL],  G = R V  [d3 x d3]
    for (int m=0;m<d3;m++) for (int c=0;c<DL;c++){
        double s=0; for (int u=0;u<DL;u++) s += sV[t][u][m]*sGL[t][u][c];
        sR[t][m][c]=s;
    }
    for (int m=0;m<d3;m++) for (int m2=0;m2<d3;m2++){
        double s=0; for (int c=0;c<DL;c++) s += sR[t][m][c]*sV[t][c][m2];
        sG[t][m][m2]=s;
    }

    // Gauss-Jordan: solve G * P = R in place (R becomes projector P [d3 x DL])
    for (int c=0;c<d3;c++){
        int piv=c; double mx=fabs(sG[t][c][c]);
        for (int r=c+1;r<d3;r++){ double v=fabs(sG[t][r][c]); if (v>mx){mx=v;piv=r;} }
        if (piv!=c){
            for (int q=0;q<d3;q++){ double tmp=sG[t][c][q]; sG[t][c][q]=sG[t][piv][q]; sG[t][piv][q]=tmp; }
            for (int q=0;q<DL;q++){ double tmp=sR[t][c][q]; sR[t][c][q]=sR[t][piv][q]; sR[t][piv][q]=tmp; }
        }
        double inv = 1.0/sG[t][c][c];
        for (int q=0;q<d3;q++) sG[t][c][q]*=inv;
        for (int q=0;q<DL;q++) sR[t][c][q]*=inv;
        for (int r=0;r<d3;r++){
            if (r==c) continue;
            double f = sG[t][r][c];
            if (f==0.0) continue;
            for (int q=0;q<d3;q++) sG[t][r][q] -= f*sG[t][c][q];
            for (int q=0;q<DL;q++) sR[t][r][q] -= f*sR[t][c][q];
        }
    }

    // CG assembly: C[m1,m2,k] = P @ tL(m1,m2)
    const int D1cnt = (l1+1)*(l1+2)/2;
    const int D2cnt = (l2+1)*(l2+2)/2;
    int a1s[6], b1s[6], a2s[6], b2s[6];
    { int n=0; for(int a=l1;a>=0;a--) for(int b=l1-a;b>=0;b--){ a1s[n]=a; b1s[n]=b; n++; } }
    { int n=0; for(int a=l2;a>=0;a--) for(int b=l2-a;b>=0;b--){ a2s[n]=a; b2s[n]=b; n++; } }

    for (int m1=0;m1<d1;m1++){
        for (int m2=0;m2<d2;m2++){
            double tL[15];
            for (int q=0;q<DL;q++) tL[q]=0.0;
            for (int i1=0;i1<D1cnt;i1++){
                double bv1 = d_getB(l1, i1, m1, B2);
                if (bv1==0.0) continue;
                for (int i2=0;i2<D2cnt;i2++){
                    double bv2 = d_getB(l2, i2, m2, B2);
                    if (bv2==0.0) continue;
                    int row = d_cidx(L, a1s[i1]+a2s[i2], b1s[i1]+b2s[i2]);
                    tL[row] += bv1*bv2;
                }
            }
            for (int k=0;k<d3;k++){
                double s=0;
                for (int c=0;c<DL;c++) s += sR[t][k][c]*tL[c];
                g_hctp_cg[t*125 + (m1*d2+m2)*d3 + k] = (float)s;
            }
        }
    }
}

// ---------------------------------------------------------------------------
// weight transpose: w[p][o][i][j] -> wT[p][i][j][o]
// ---------------------------------------------------------------------------
__global__ void hctp_transpose(const float* __restrict__ w){
    __shared__ float tile[64][65];
    const int i = blockIdx.x;
    const int p = blockIdx.y;
    const int t = threadIdx.x;
    const float* wp = w + ((size_t)p << 18);
    {
        int j = t & 63, o0 = t >> 6;
        #pragma unroll
        for (int s=0;s<16;s++){
            int o = o0 + s*4;
            tile[o][j] = wp[o*4096 + i*64 + j];
        }
    }
    __syncthreads();
    {
        int o = t & 63, j0 = t >> 6;
        float* dst = g_hctp_wT + ((size_t)p << 18) + ((size_t)i << 12);
        #pragma unroll
        for (int s=0;s<16;s++){
            int j = j0 + s*4;
            dst[j*64 + o] = tile[o][j];
        }
    }
}

// ---------------------------------------------------------------------------
// zero output
// ---------------------------------------------------------------------------
__global__ void hctp_zero(float* __restrict__ out, size_t n){
    size_t i = (size_t)blockIdx.x * blockDim.x + threadIdx.x;
    size_t stride = (size_t)gridDim.x * blockDim.x;
    for (; i < n; i += stride) out[i] = 0.f;
}

// ---------------------------------------------------------------------------
// main per-path kernel
// ---------------------------------------------------------------------------
constexpr int tp_smem_floats(int l1,int l2,int l3){
    int d1=2*l1+1, d2=2*l2+1, d3=2*l3+1;
    return 16*(64*d1+1) + 16*(64*d2+1) + 4096 + d3*1024 + d1*d2*d3;
}

template<int L1,int L2,int L3,int P>
__global__ void __launch_bounds__(256,2) tp_kernel(
    const float* __restrict__ x1, const float* __restrict__ x2,
    float* __restrict__ out, int n)
{
    constexpr int D1=2*L1+1, D2=2*L2+1, D3=2*L3+1;
    constexpr int K0 = (L3==0)?0:((L3==1)?1:4);
    constexpr int NB=16;
    constexpr int S1 = 64*D1+1, S2 = 64*D2+1;
    constexpr int CH1 = 64*D1, CH2 = 64*D2;

    extern __shared__ float sm[];
    float* sX1 = sm;                  // NB*S1
    float* sX2 = sX1 + NB*S1;         // NB*S2
    float* sW  = sX2 + NB*S2;         // 4096
    float* sZ  = sW + 4096;           // D3*1024 : sZ[k][j*16+b]
    float* sCG = sZ + D3*1024;        // D1*D2*D3

    const int t = threadIdx.x;
    const int B0 = blockIdx.x * NB;

    for (int q=t; q<D1*D2*D3; q+=256) sCG[q] = g_hctp_cg[P*125+q];
    for (int q=t; q<NB*CH1; q+=256){
        int b = q / CH1, rem = q - b*CH1;
        sX1[b*S1 + rem] = (B0+b < n) ? x1[(size_t)(B0+b)*CH1 + rem] : 0.f;
    }
    for (int q=t; q<NB*CH2; q+=256){
        int b = q / CH2, rem = q - b*CH2;
        sX2[b*S2 + rem] = (B0+b < n) ? x2[(size_t)(B0+b)*CH2 + rem] : 0.f;
    }
    __syncthreads();

    // FMA-phase mapping: lanes 0-15 share b, og varies -> w LDS.128 conflict-free,
    // z reads broadcast. Each warp owns 2 batch elements.
    const int lane = t & 31, wrp = t >> 5;
    const int og = lane & 15;
    const int bF = wrp*2 + (lane>>4);
    // Z-phase mapping
    const int bZ = t & 15, jg = t >> 4;

    const float* wTp = g_hctp_wT + ((size_t)P << 18);

    float acc[4][D3];
    #pragma unroll
    for (int oo=0;oo<4;oo++)
        #pragma unroll
        for (int k=0;k<D3;k++) acc[oo][k]=0.f;

    for (int i=0;i<64;i++){
        __syncthreads();  // protect sW/sZ from previous iteration's readers

        // stage w[j][o] tile for this i
        {
            const float4* src = (const float4*)(wTp + (size_t)i*4096);
            float4* dst = (float4*)sW;
            for (int q=t; q<1024; q+=256) dst[q] = src[q];
        }

        // z phase: t[n][k] = sum_m x1[bZ,i,m]*CG[m,n,k]; z = t . x2
        {
            float a_[D1];
            #pragma unroll
            for (int m=0;m<D1;m++) a_[m] = sX1[bZ*S1 + i*D1 + m];
            float tt[D2][D3];
            #pragma unroll
            for (int nn=0;nn<D2;nn++)
                #pragma unroll
                for (int k=0;k<D3;k++) tt[nn][k]=0.f;
            #pragma unroll
            for (int m=0;m<D1;m++)
                #pragma unroll
                for (int nn=0;nn<D2;nn++)
                    #pragma unroll
                    for (int k=0;k<D3;k++){
                        float c = sCG[(m*D2+nn)*D3+k];
                        if (c != 0.f) tt[nn][k] += c*a_[m];
                    }
            #pragma unroll
            for (int jj=0;jj<4;jj++){
                int j = jg*4+jj;
                float xv[D2];
                #pragma unroll
                for (int nn=0;nn<D2;nn++) xv[nn] = sX2[bZ*S2 + j*D2 + nn];
                #pragma unroll
                for (int k=0;k<D3;k++){
                    float z=0.f;
                    #pragma unroll
                    for (int nn=0;nn<D2;nn++) z += tt[nn][k]*xv[nn];
                    sZ[k*1024 + j*16 + bZ] = z;
                }
            }
        }
        __syncthreads();

        // FMA phase: rank-64 update
        #pragma unroll 4
        for (int j=0;j<64;j++){
            const float4 w4 = *(const float4*)(sW + j*64 + og*4);
            float zv[D3];
            #pragma unroll
            for (int k=0;k<D3;k++) zv[k] = sZ[k*1024 + j*16 + bF];
            #pragma unroll
            for (int k=0;k<D3;k++){
                acc[0][k] += w4.x*zv[k];
                acc[1][k] += w4.y*zv[k];
                acc[2][k] += w4.z*zv[k];
                acc[3][k] += w4.w*zv[k];
            }
        }
    }

    if (B0+bF < n){
        float* ob = out + (size_t)(B0+bF)*576 + K0;
        #pragma unroll
        for (int oo=0;oo<4;oo++){
            float* op = ob + (og*4+oo)*9;
            #pragma unroll
            for (int k=0;k<D3;k++) op[k] += acc[oo][k];
        }
    }
}

// ---------------------------------------------------------------------------
// launch — operand identification is SIZE-BASED, robust to metadata ordering.
// setup_inputs() inserts x1_l0, x2_l0, x1_l1, x2_l1, x1_l2, x2_l2, weight
// (interleaved!), so never assume signature order.
// ---------------------------------------------------------------------------
extern "C" void kernel_launch(void* const* d_in, const int* in_sizes, int n_in,
                              void* d_out, int out_size){
    const long long WELEMS = (long long)NPATH * 64 * 64 * 64;  // 2,883,584

    // find weight: the unique input whose size appears exactly once (== WELEMS)
    const float* w = nullptr;
    long long minOther = 0x7fffffffffffLL;
    for (int i = 0; i < n_in; i++){
        if ((long long)in_sizes[i] == WELEMS && w == nullptr) { w = (const float*)d_in[i]; }
    }
    for (int i = 0; i < n_in; i++){
        if ((const float*)d_in[i] == w) continue;
        if ((long long)in_sizes[i] < minOther) minOther = in_sizes[i];
    }
    const int nvec = (int)(minOther / 64);   // N  (l0 input is N*64*1)

    // assign x1/x2 per l by size; first occurrence = x1, second = x2
    const float* x1p[3] = {nullptr,nullptr,nullptr};
    const float* x2p[3] = {nullptr,nullptr,nullptr};
    for (int i = 0; i < n_in; i++){
        const float* ptr = (const float*)d_in[i];
        if (ptr == w) continue;
        long long sz = in_sizes[i];
        for (int l = 0; l < 3; l++){
            if (sz == (long long)nvec * 64 * (2*l+1)){
                if (!x1p[l]) x1p[l] = ptr; else x2p[l] = ptr;
                break;
            }
        }
    }

    float* out = (float*)d_out;
    const int nb = (nvec + 15) / 16;

    hctp_build_cg<<<1, 32>>>();
    hctp_transpose<<<dim3(64, NPATH), 256>>>(w);
    hctp_zero<<<1024, 256>>>(out, (size_t)nvec*576);

#define LAUNCH_PATH(P,L1,L2,L3) do { \
    constexpr int smem = tp_smem_floats(L1,L2,L3) * 4; \
    cudaFuncSetAttribute(tp_kernel<L1,L2,L3,P>, cudaFuncAttributeMaxDynamicSharedMemorySize, smem); \
    tp_kernel<L1,L2,L3,P><<<nb, 256, smem>>>(x1p[L1], x2p[L2], out, nvec); \
} while(0)

    LAUNCH_PATH(0, 0,0,0);
    LAUNCH_PATH(1, 0,1,1);
    LAUNCH_PATH(2, 0,2,2);
    LAUNCH_PATH(3, 1,0,1);
    LAUNCH_PATH(4, 1,1,0);
    LAUNCH_PATH(5, 1,1,2);
    LAUNCH_PATH(6, 1,2,1);
    LAUNCH_PATH(7, 2,0,2);
    LAUNCH_PATH(8, 2,1,1);
    LAUNCH_PATH(9, 2,2,0);
    LAUNCH_PATH(10,2,2,2);
#undef LAUNCH_PATH
}

// round 4
// speedup vs baseline: 1.1341x; 1.1341x over previous
#include <cuda_runtime.h>
#include <math.h>
#include <stdint.h>

#define NPATH 11

// ---------------------------------------------------------------------------
// device globals (no allocation allowed)
// ---------------------------------------------------------------------------
__device__ float g_hctp_cg[NPATH * 125];            // compact [p][(m1*d2+m2)*d3+k]

// ---------------------------------------------------------------------------
// CG builder (fp64, replicates numpy pipeline; l=2 basis analytic from LAPACK)
// VERIFIED correct (rel_err 1.16e-6) — do not touch.
// ---------------------------------------------------------------------------
__device__ __forceinline__ double d_fact(int n){ double f=1; for(int i=2;i<=n;i++) f*=i; return f; }
__device__ __forceinline__ double d_dfact(int n){ double o=1; for(int k=n;k>0;k-=2) o*=k; return o; }
__device__ __forceinline__ double d_gmom(int n){ return (n&1) ? 0.0 : d_dfact(n-1); }
__device__ __forceinline__ int d_cidx(int L,int a,int b){ int t=L-a; return t*(t+1)/2 + (t-b); }

__device__ __forceinline__ double d_getB(int l, int i, int m, const double B2[6][5]){
    if (l==0) return 1.0;
    if (l==1) return (i==m) ? 1.0 : 0.0;
    return B2[i][m];
}

__global__ void hctp_build_cg(){
    __shared__ double sGL[NPATH][15][15];
    __shared__ double sV [NPATH][15][5];
    __shared__ double sR [NPATH][5][15];
    __shared__ double sG [NPATH][5][5];

    const int t = threadIdx.x;
    if (t >= NPATH) return;

    const int L1t[NPATH]={0,0,0,1,1,1,1,2,2,2,2};
    const int L2t[NPATH]={0,1,2,0,1,1,2,0,1,2,2};
    const int L3t[NPATH]={0,1,2,1,0,2,1,2,1,0,2};
    const int l1=L1t[t], l2=L2t[t], l3=L3t[t];
    const int L = l1 + l2;
    const int DL = (L+1)*(L+2)/2;
    const int d1 = 2*l1+1, d2 = 2*l2+1, d3 = 2*l3+1;

    double B2[6][5];
    for (int i=0;i<6;i++) for (int m=0;m<5;m++) B2[i][m]=0.0;
    {
        double s3 = sqrt(3.0), s2 = sqrt(2.0), s6 = sqrt(6.0);
        double pp = (3.0+s3)/(6.0*s2);
        double qq = (3.0-s3)/(6.0*s2);
        double rr = 1.0/s6;
        B2[1][0]=1.0;  B2[2][1]=1.0;  B2[4][3]=1.0;
        B2[0][2]=-rr;  B2[3][2]= pp;  B2[5][2]=-qq;
        B2[0][4]=-rr;  B2[3][4]=-qq;  B2[5][4]= pp;
    }

    int ca[15], cb[15];
    { int n=0; for(int a=L;a>=0;a--) for(int b=L-a;b>=0;b--){ ca[n]=a; cb[n]=b; n++; } }

    for (int i=0;i<DL;i++) for (int j=0;j<DL;j++){
        int aa = ca[i]+ca[j], bb = cb[i]+cb[j];
        int cc = (L-ca[i]-cb[i]) + (L-ca[j]-cb[j]);
        sGL[t][i][j] = d_gmom(aa)*d_gmom(bb)*d_gmom(cc);
    }

    const int kr = (L - l3)/2;
    const int Dl = (l3+1)*(l3+2)/2;
    int la[6], lb[6];
    { int n=0; for(int a=l3;a>=0;a--) for(int b=l3-a;b>=0;b--){ la[n]=a; lb[n]=b; n++; } }
    for (int i=0;i<DL;i++) for (int m=0;m<d3;m++) sV[t][i][m]=0.0;
    for (int j=0;j<Dl;j++){
        for (int p=0;p<=kr;p++) for (int q=0;q<=kr-p;q++){
            int r = kr - p - q;
            double coef = d_fact(kr)/(d_fact(p)*d_fact(q)*d_fact(r));
            int row = d_cidx(L, la[j]+2*p, lb[j]+2*q);
            for (int m=0;m<d3;m++) sV[t][row][m] += coef * d_getB(l3, j, m, B2);
        }
    }

    for (int m=0;m<d3;m++) for (int c=0;c<DL;c++){
        double s=0; for (int u=0;u<DL;u++) s += sV[t][u][m]*sGL[t][u][c];
        sR[t][m][c]=s;
    }
    for (int m=0;m<d3;m++) for (int m2=0;m2<d3;m2++){
        double s=0; for (int c=0;c<DL;c++) s += sR[t][m][c]*sV[t][c][m2];
        sG[t][m][m2]=s;
    }

    for (int c=0;c<d3;c++){
        int piv=c; double mx=fabs(sG[t][c][c]);
        for (int r=c+1;r<d3;r++){ double v=fabs(sG[t][r][c]); if (v>mx){mx=v;piv=r;} }
        if (piv!=c){
            for (int q=0;q<d3;q++){ double tmp=sG[t][c][q]; sG[t][c][q]=sG[t][piv][q]; sG[t][piv][q]=tmp; }
            for (int q=0;q<DL;q++){ double tmp=sR[t][c][q]; sR[t][c][q]=sR[t][piv][q]; sR[t][piv][q]=tmp; }
        }
        double inv = 1.0/sG[t][c][c];
        for (int q=0;q<d3;q++) sG[t][c][q]*=inv;
        for (int q=0;q<DL;q++) sR[t][c][q]*=inv;
        for (int r=0;r<d3;r++){
            if (r==c) continue;
            double f = sG[t][r][c];
            if (f==0.0) continue;
            for (int q=0;q<d3;q++) sG[t][r][q] -= f*sG[t][c][q];
            for (int q=0;q<DL;q++) sR[t][r][q] -= f*sR[t][c][q];
        }
    }

    const int D1cnt = (l1+1)*(l1+2)/2;
    const int D2cnt = (l2+1)*(l2+2)/2;
    int a1s[6], b1s[6], a2s[6], b2s[6];
    { int n=0; for(int a=l1;a>=0;a--) for(int b=l1-a;b>=0;b--){ a1s[n]=a; b1s[n]=b; n++; } }
    { int n=0; for(int a=l2;a>=0;a--) for(int b=l2-a;b>=0;b--){ a2s[n]=a; b2s[n]=b; n++; } }

    for (int m1=0;m1<d1;m1++){
        for (int m2=0;m2<d2;m2++){
            double tL[15];
            for (int q=0;q<DL;q++) tL[q]=0.0;
            for (int i1=0;i1<D1cnt;i1++){
                double bv1 = d_getB(l1, i1, m1, B2);
                if (bv1==0.0) continue;
                for (int i2=0;i2<D2cnt;i2++){
                    double bv2 = d_getB(l2, i2, m2, B2);
                    if (bv2==0.0) continue;
                    int row = d_cidx(L, a1s[i1]+a2s[i2], b1s[i1]+b2s[i2]);
                    tL[row] += bv1*bv2;
                }
            }
            for (int k=0;k<d3;k++){
                double s=0;
                for (int c=0;c<DL;c++) s += sR[t][k][c]*tL[c];
                g_hctp_cg[t*125 + (m1*d2+m2)*d3 + k] = (float)s;
            }
        }
    }
}

// ---------------------------------------------------------------------------
// zero output
// ---------------------------------------------------------------------------
__global__ void hctp_zero(float* __restrict__ out, size_t n){
    size_t i = (size_t)blockIdx.x * blockDim.x + threadIdx.x;
    size_t stride = (size_t)gridDim.x * blockDim.x;
    for (; i < n; i += stride) out[i] = 0.f;
}

// ---------------------------------------------------------------------------
// main per-path kernel — j-paired f32x2 rank-update
// ---------------------------------------------------------------------------
constexpr int tp_smem_floats(int l1,int l2,int l3){
    int d1=2*l1+1, d2=2*l2+1, d3=2*l3+1;
    return 16*(64*d1+1) + 16*(64*d2+1) + 64*66 + d3*16*66 + d1*d2*d3;
}

__device__ __forceinline__ void ffma2(unsigned long long& acc,
                                      unsigned long long a,
                                      unsigned long long b){
    asm("fma.rn.f32x2 %0, %1, %2, %0;" : "+l"(acc) : "l"(a), "l"(b));
}

template<int L1,int L2,int L3,int P>
__global__ void __launch_bounds__(256,2) tp_kernel(
    const float* __restrict__ x1, const float* __restrict__ x2,
    const float* __restrict__ w,  float* __restrict__ out, int n)
{
    constexpr int D1=2*L1+1, D2=2*L2+1, D3=2*L3+1;
    constexpr int K0 = (L3==0)?0:((L3==1)?1:4);
    constexpr int NB=16;
    constexpr int S1 = 64*D1+1, S2 = 64*D2+1;
    constexpr int CH1 = 64*D1, CH2 = 64*D2;
    constexpr int WST = 66;                 // sW row stride ([o][j])
    constexpr int ZST = 66;                 // sZ row stride ([k][b][j])

    extern __shared__ float sm[];
    float* sX1 = sm;                        // NB*S1
    float* sX2 = sX1 + NB*S1;               // NB*S2
    float* sW  = sX2 + NB*S2;               // 64*WST
    float* sZ  = sW + 64*WST;               // D3*16*ZST
    float* sCG = sZ + D3*16*ZST;            // D1*D2*D3

    const int t = threadIdx.x;
    const int B0 = blockIdx.x * NB;

    for (int q=t; q<D1*D2*D3; q+=256) sCG[q] = g_hctp_cg[P*125+q];
    for (int q=t; q<NB*CH1; q+=256){
        int b = q / CH1, rem = q - b*CH1;
        sX1[b*S1 + rem] = (B0+b < n) ? x1[(size_t)(B0+b)*CH1 + rem] : 0.f;
    }
    for (int q=t; q<NB*CH2; q+=256){
        int b = q / CH2, rem = q - b*CH2;
        sX2[b*S2 + rem] = (B0+b < n) ? x2[(size_t)(B0+b)*CH2 + rem] : 0.f;
    }
    __syncthreads();

    // FMA-phase mapping: lanes 0-15 (og) pick o = og + 16*oo (conflict-free
    // LDS.64 on the stride-66 [o][j] tile); each warp owns 2 batch elements.
    const int lane = t & 31, wrp = t >> 5;
    const int og = lane & 15;
    const int bF = wrp*2 + (lane>>4);
    // Z-phase mapping
    const int bZ = t & 15, jg = t >> 4;

    const float* wp = w + ((size_t)P << 18);

    unsigned long long acc2[4][D3];
    #pragma unroll
    for (int oo=0;oo<4;oo++)
        #pragma unroll
        for (int k=0;k<D3;k++) acc2[oo][k]=0ull;

    for (int i=0;i<64;i++){
        __syncthreads();  // prev FMA readers of sW/sZ done

        // prefetch this i's w tile into registers (L2 latency hidden by z-phase)
        float4 wreg[4];
        #pragma unroll
        for (int s=0;s<4;s++){
            int q = t + s*256;                    // 0..1023
            int o = q >> 4, j4 = (q & 15) << 2;
            wreg[s] = *(const float4*)(wp + (size_t)o*4096 + i*64 + j4);
        }

        // z phase: t[n][k] = sum_m x1[bZ,i,m]*CG[m,n,k]; z = t . x2
        {
            float a_[D1];
            #pragma unroll
            for (int m=0;m<D1;m++) a_[m] = sX1[bZ*S1 + i*D1 + m];
            float tt[D2][D3];
            #pragma unroll
            for (int nn=0;nn<D2;nn++)
                #pragma unroll
                for (int k=0;k<D3;k++) tt[nn][k]=0.f;
            #pragma unroll
            for (int m=0;m<D1;m++)
                #pragma unroll
                for (int nn=0;nn<D2;nn++)
                    #pragma unroll
                    for (int k=0;k<D3;k++){
                        float c = sCG[(m*D2+nn)*D3+k];
                        tt[nn][k] += c*a_[m];
                    }
            #pragma unroll
            for (int jj=0;jj<4;jj++){
                int j = jg*4+jj;
                float xv[D2];
                #pragma unroll
                for (int nn=0;nn<D2;nn++) xv[nn] = sX2[bZ*S2 + j*D2 + nn];
                #pragma unroll
                for (int k=0;k<D3;k++){
                    float z=0.f;
                    #pragma unroll
                    for (int nn=0;nn<D2;nn++) z += tt[nn][k]*xv[nn];
                    sZ[(k*16 + bZ)*ZST + j] = z;
                }
            }
        }

        // store w tile: sW[o][j], stride 66 (STS.64 pairs; stride 66 keeps
        // the FMA-phase LDS.64 conflict-free)
        #pragma unroll
        for (int s=0;s<4;s++){
            int q = t + s*256;
            int o = q >> 4, j4 = (q & 15) << 2;
            float* d = sW + o*WST + j4;
            *(float2*)(d)   = make_float2(wreg[s].x, wreg[s].y);
            *(float2*)(d+2) = make_float2(wreg[s].z, wreg[s].w);
        }
        __syncthreads();

        // FMA phase: rank-64 update, j packed in pairs via fma.rn.f32x2
        const float* zb = sZ + bF*ZST;
        #pragma unroll 4
        for (int jp=0;jp<32;jp++){
            unsigned long long w2[4], z2[D3];
            #pragma unroll
            for (int oo=0;oo<4;oo++)
                w2[oo] = *(const unsigned long long*)(sW + (og+16*oo)*WST + 2*jp);
            #pragma unroll
            for (int k=0;k<D3;k++)
                z2[k] = *(const unsigned long long*)(zb + k*16*ZST + 2*jp);
            #pragma unroll
            for (int oo=0;oo<4;oo++)
                #pragma unroll
                for (int k=0;k<D3;k++)
                    ffma2(acc2[oo][k], w2[oo], z2[k]);
        }
    }

    if (B0+bF < n){
        float* ob = out + (size_t)(B0+bF)*576 + K0;
        #pragma unroll
        for (int oo=0;oo<4;oo++){
            int o = og + 16*oo;
            #pragma unroll
            for (int k=0;k<D3;k++){
                unsigned long long v = acc2[oo][k];
                float lo = __uint_as_float((unsigned int)v);
                float hi = __uint_as_float((unsigned int)(v >> 32));
                ob[o*9 + k] += lo + hi;
            }
        }
    }
}

// ---------------------------------------------------------------------------
// launch — operand identification is SIZE-BASED (metadata order interleaves
// x1_l0, x2_l0, x1_l1, x2_l1, x1_l2, x2_l2, weight).
// ---------------------------------------------------------------------------
extern "C" void kernel_launch(void* const* d_in, const int* in_sizes, int n_in,
                              void* d_out, int out_size){
    const long long WELEMS = (long long)NPATH * 64 * 64 * 64;  // 2,883,584

    const float* w = nullptr;
    long long minOther = 0x7fffffffffffLL;
    for (int i = 0; i < n_in; i++){
        if ((long long)in_sizes[i] == WELEMS && w == nullptr) { w = (const float*)d_in[i]; }
    }
    for (int i = 0; i < n_in; i++){
        if ((const float*)d_in[i] == w) continue;
        if ((long long)in_sizes[i] < minOther) minOther = in_sizes[i];
    }
    const int nvec = (int)(minOther / 64);   // N  (l0 input is N*64*1)

    const float* x1p[3] = {nullptr,nullptr,nullptr};
    const float* x2p[3] = {nullptr,nullptr,nullptr};
    for (int i = 0; i < n_in; i++){
        const float* ptr = (const float*)d_in[i];
        if (ptr == w) continue;
        long long sz = in_sizes[i];
        for (int l = 0; l < 3; l++){
            if (sz == (long long)nvec * 64 * (2*l+1)){
                if (!x1p[l]) x1p[l] = ptr; else x2p[l] = ptr;
                break;
            }
        }
    }

    float* out = (float*)d_out;
    const int nb = (nvec + 15) / 16;

    hctp_build_cg<<<1, 32>>>();
    hctp_zero<<<1024, 256>>>(out, (size_t)nvec*576);

#define LAUNCH_PATH(Pp,L1,L2,L3) do { \
    constexpr int smem = tp_smem_floats(L1,L2,L3) * 4; \
    cudaFuncSetAttribute(tp_kernel<L1,L2,L3,Pp>, cudaFuncAttributeMaxDynamicSharedMemorySize, smem); \
    tp_kernel<L1,L2,L3,Pp><<<nb, 256, smem>>>(x1p[L1], x2p[L2], w, out, nvec); \
} while(0)

    LAUNCH_PATH(0, 0,0,0);
    LAUNCH_PATH(1, 0,1,1);
    LAUNCH_PATH(2, 0,2,2);
    LAUNCH_PATH(3, 1,0,1);
    LAUNCH_PATH(4, 1,1,0);
    LAUNCH_PATH(5, 1,1,2);
    LAUNCH_PATH(6, 1,2,1);
    LAUNCH_PATH(7, 2,0,2);
    LAUNCH_PATH(8, 2,1,1);
    LAUNCH_PATH(9, 2,2,0);
    LAUNCH_PATH(10,2,2,2);
#undef LAUNCH_PATH
}

// round 5
// speedup vs baseline: 1.1467x; 1.0111x over previous
#include <cuda_runtime.h>
#include <math.h>
#include <stdint.h>

#define NPATH 11

// ---------------------------------------------------------------------------
// device globals (no allocation allowed)
// ---------------------------------------------------------------------------
__device__ float g_hctp_cg[NPATH * 125];            // compact [p][(m1*d2+m2)*d3+k]

// ---------------------------------------------------------------------------
// CG builder (fp64, replicates numpy pipeline; l=2 basis analytic from LAPACK)
// VERIFIED correct (rel_err ~1e-6) — do not touch.
// ---------------------------------------------------------------------------
__device__ __forceinline__ double d_fact(int n){ double f=1; for(int i=2;i<=n;i++) f*=i; return f; }
__device__ __forceinline__ double d_dfact(int n){ double o=1; for(int k=n;k>0;k-=2) o*=k; return o; }
__device__ __forceinline__ double d_gmom(int n){ return (n&1) ? 0.0 : d_dfact(n-1); }
__device__ __forceinline__ int d_cidx(int L,int a,int b){ int t=L-a; return t*(t+1)/2 + (t-b); }

__device__ __forceinline__ double d_getB(int l, int i, int m, const double B2[6][5]){
    if (l==0) return 1.0;
    if (l==1) return (i==m) ? 1.0 : 0.0;
    return B2[i][m];
}

__global__ void hctp_build_cg(){
    __shared__ double sGL[NPATH][15][15];
    __shared__ double sV [NPATH][15][5];
    __shared__ double sR [NPATH][5][15];
    __shared__ double sG [NPATH][5][5];

    const int t = threadIdx.x;
    if (t >= NPATH) return;

    const int L1t[NPATH]={0,0,0,1,1,1,1,2,2,2,2};
    const int L2t[NPATH]={0,1,2,0,1,1,2,0,1,2,2};
    const int L3t[NPATH]={0,1,2,1,0,2,1,2,1,0,2};
    const int l1=L1t[t], l2=L2t[t], l3=L3t[t];
    const int L = l1 + l2;
    const int DL = (L+1)*(L+2)/2;
    const int d1 = 2*l1+1, d2 = 2*l2+1, d3 = 2*l3+1;

    double B2[6][5];
    for (int i=0;i<6;i++) for (int m=0;m<5;m++) B2[i][m]=0.0;
    {
        double s3 = sqrt(3.0), s2 = sqrt(2.0), s6 = sqrt(6.0);
        double pp = (3.0+s3)/(6.0*s2);
        double qq = (3.0-s3)/(6.0*s2);
        double rr = 1.0/s6;
        B2[1][0]=1.0;  B2[2][1]=1.0;  B2[4][3]=1.0;
        B2[0][2]=-rr;  B2[3][2]= pp;  B2[5][2]=-qq;
        B2[0][4]=-rr;  B2[3][4]=-qq;  B2[5][4]= pp;
    }

    int ca[15], cb[15];
    { int n=0; for(int a=L;a>=0;a--) for(int b=L-a;b>=0;b--){ ca[n]=a; cb[n]=b; n++; } }

    for (int i=0;i<DL;i++) for (int j=0;j<DL;j++){
        int aa = ca[i]+ca[j], bb = cb[i]+cb[j];
        int cc = (L-ca[i]-cb[i]) + (L-ca[j]-cb[j]);
        sGL[t][i][j] = d_gmom(aa)*d_gmom(bb)*d_gmom(cc);
    }

    const int kr = (L - l3)/2;
    const int Dl = (l3+1)*(l3+2)/2;
    int la[6], lb[6];
    { int n=0; for(int a=l3;a>=0;a--) for(int b=l3-a;b>=0;b--){ la[n]=a; lb[n]=b; n++; } }
    for (int i=0;i<DL;i++) for (int m=0;m<d3;m++) sV[t][i][m]=0.0;
    for (int j=0;j<Dl;j++){
        for (int p=0;p<=kr;p++) for (int q=0;q<=kr-p;q++){
            int r = kr - p - q;
            double coef = d_fact(kr)/(d_fact(p)*d_fact(q)*d_fact(r));
            int row = d_cidx(L, la[j]+2*p, lb[j]+2*q);
            for (int m=0;m<d3;m++) sV[t][row][m] += coef * d_getB(l3, j, m, B2);
        }
    }

    for (int m=0;m<d3;m++) for (int c=0;c<DL;c++){
        double s=0; for (int u=0;u<DL;u++) s += sV[t][u][m]*sGL[t][u][c];
        sR[t][m][c]=s;
    }
    for (int m=0;m<d3;m++) for (int m2=0;m2<d3;m2++){
        double s=0; for (int c=0;c<DL;c++) s += sR[t][m][c]*sV[t][c][m2];
        sG[t][m][m2]=s;
    }

    for (int c=0;c<d3;c++){
        int piv=c; double mx=fabs(sG[t][c][c]);
        for (int r=c+1;r<d3;r++){ double v=fabs(sG[t][r][c]); if (v>mx){mx=v;piv=r;} }
        if (piv!=c){
            for (int q=0;q<d3;q++){ double tmp=sG[t][c][q]; sG[t][c][q]=sG[t][piv][q]; sG[t][piv][q]=tmp; }
            for (int q=0;q<DL;q++){ double tmp=sR[t][c][q]; sR[t][c][q]=sR[t][piv][q]; sR[t][piv][q]=tmp; }
        }
        double inv = 1.0/sG[t][c][c];
        for (int q=0;q<d3;q++) sG[t][c][q]*=inv;
        for (int q=0;q<DL;q++) sR[t][c][q]*=inv;
        for (int r=0;r<d3;r++){
            if (r==c) continue;
            double f = sG[t][r][c];
            if (f==0.0) continue;
            for (int q=0;q<d3;q++) sG[t][r][q] -= f*sG[t][c][q];
            for (int q=0;q<DL;q++) sR[t][r][q] -= f*sR[t][c][q];
        }
    }

    const int D1cnt = (l1+1)*(l1+2)/2;
    const int D2cnt = (l2+1)*(l2+2)/2;
    int a1s[6], b1s[6], a2s[6], b2s[6];
    { int n=0; for(int a=l1;a>=0;a--) for(int b=l1-a;b>=0;b--){ a1s[n]=a; b1s[n]=b; n++; } }
    { int n=0; for(int a=l2;a>=0;a--) for(int b=l2-a;b>=0;b--){ a2s[n]=a; b2s[n]=b; n++; } }

    for (int m1=0;m1<d1;m1++){
        for (int m2=0;m2<d2;m2++){
            double tL[15];
            for (int q=0;q<DL;q++) tL[q]=0.0;
            for (int i1=0;i1<D1cnt;i1++){
                double bv1 = d_getB(l1, i1, m1, B2);
                if (bv1==0.0) continue;
                for (int i2=0;i2<D2cnt;i2++){
                    double bv2 = d_getB(l2, i2, m2, B2);
                    if (bv2==0.0) continue;
                    int row = d_cidx(L, a1s[i1]+a2s[i2], b1s[i1]+b2s[i2]);
                    tL[row] += bv1*bv2;
                }
            }
            for (int k=0;k<d3;k++){
                double s=0;
                for (int c=0;c<DL;c++) s += sR[t][k][c]*tL[c];
                g_hctp_cg[t*125 + (m1*d2+m2)*d3 + k] = (float)s;
            }
        }
    }
}

// ---------------------------------------------------------------------------
// zero output
// ---------------------------------------------------------------------------
__global__ void hctp_zero(float* __restrict__ out, size_t n){
    size_t i = (size_t)blockIdx.x * blockDim.x + threadIdx.x;
    size_t stride = (size_t)gridDim.x * blockDim.x;
    for (; i < n; i += stride) out[i] = 0.f;
}

// ---------------------------------------------------------------------------
// main per-path kernel — j-paired f32x2 rank-update, LDS.128 operand loads
// ---------------------------------------------------------------------------
constexpr int tp_smem_floats(int l1,int l2,int l3){
    int d1=2*l1+1, d2=2*l2+1, d3=2*l3+1;
    return 16*(64*d1+1) + 16*(64*d2+1) + 64*68 + d3*16*68 + d1*d2*d3;
}

__device__ __forceinline__ void ffma2(unsigned long long& acc,
                                      unsigned long long a,
                                      unsigned long long b){
    asm("fma.rn.f32x2 %0, %1, %2, %0;" : "+l"(acc) : "l"(a), "l"(b));
}

template<int L1,int L2,int L3,int P>
__global__ void __launch_bounds__(256,2) tp_kernel(
    const float* __restrict__ x1, const float* __restrict__ x2,
    const float* __restrict__ w,  float* __restrict__ out, int n)
{
    constexpr int D1=2*L1+1, D2=2*L2+1, D3=2*L3+1;
    constexpr int K0 = (L3==0)?0:((L3==1)?1:4);
    constexpr int NB=16;
    constexpr int S1 = 64*D1+1, S2 = 64*D2+1;
    constexpr int CH1 = 64*D1, CH2 = 64*D2;
    constexpr int WST = 68;                 // sW row stride ([o][j]) — 272B, 16B-aligned
    constexpr int ZST = 68;                 // sZ row stride ([k*16+b][j])

    extern __shared__ float sm[];
    float* sX1 = sm;                        // NB*S1
    float* sX2 = sX1 + NB*S1;               // NB*S2
    float* sW  = sX2 + NB*S2;               // 64*WST
    float* sZ  = sW + 64*WST;               // D3*16*ZST
    float* sCG = sZ + D3*16*ZST;            // D1*D2*D3

    const int t = threadIdx.x;
    const int B0 = blockIdx.x * NB;

    for (int q=t; q<D1*D2*D3; q+=256) sCG[q] = g_hctp_cg[P*125+q];
    for (int q=t; q<NB*CH1; q+=256){
        int b = q / CH1, rem = q - b*CH1;
        sX1[b*S1 + rem] = (B0+b < n) ? x1[(size_t)(B0+b)*CH1 + rem] : 0.f;
    }
    for (int q=t; q<NB*CH2; q+=256){
        int b = q / CH2, rem = q - b*CH2;
        sX2[b*S2 + rem] = (B0+b < n) ? x2[(size_t)(B0+b)*CH2 + rem] : 0.f;
    }
    __syncthreads();

    // FMA-phase mapping: lanes 0-15 (og) pick o = og + 16*oo; w LDS.128 is
    // quad-phase conflict-free at stride 68; z LDS.128 broadcasts per half-warp.
    const int lane = t & 31, wrp = t >> 5;
    const int og = lane & 15;
    const int bF = wrp*2 + (lane>>4);
    // Z-phase mapping
    const int bZ = t & 15, jg = t >> 4;

    const float* wp = w + ((size_t)P << 18);

    unsigned long long acc2[4][D3];
    #pragma unroll
    for (int oo=0;oo<4;oo++)
        #pragma unroll
        for (int k=0;k<D3;k++) acc2[oo][k]=0ull;

    for (int i=0;i<64;i++){
        __syncthreads();  // prev FMA readers of sW/sZ done

        // prefetch this i's w tile into registers (L2 latency hidden by z-phase)
        float4 wreg[4];
        #pragma unroll
        for (int s=0;s<4;s++){
            int q = t + s*256;                    // 0..1023
            int o = q >> 4, j4 = (q & 15) << 2;
            wreg[s] = *(const float4*)(wp + (size_t)o*4096 + i*64 + j4);
        }

        // z phase: t[n][k] = sum_m x1[bZ,i,m]*CG[m,n,k]; z = t . x2
        {
            float a_[D1];
            #pragma unroll
            for (int m=0;m<D1;m++) a_[m] = sX1[bZ*S1 + i*D1 + m];
            float tt[D2][D3];
            #pragma unroll
            for (int nn=0;nn<D2;nn++)
                #pragma unroll
                for (int k=0;k<D3;k++) tt[nn][k]=0.f;
            #pragma unroll
            for (int m=0;m<D1;m++)
                #pragma unroll
                for (int nn=0;nn<D2;nn++)
                    #pragma unroll
                    for (int k=0;k<D3;k++){
                        float c = sCG[(m*D2+nn)*D3+k];
                        tt[nn][k] += c*a_[m];
                    }
            #pragma unroll
            for (int jj=0;jj<4;jj++){
                int j = jg*4+jj;
                float xv[D2];
                #pragma unroll
                for (int nn=0;nn<D2;nn++) xv[nn] = sX2[bZ*S2 + j*D2 + nn];
                #pragma unroll
                for (int k=0;k<D3;k++){
                    float z=0.f;
                    #pragma unroll
                    for (int nn=0;nn<D2;nn++) z += tt[nn][k]*xv[nn];
                    sZ[(k*16 + bZ)*ZST + j] = z;
                }
            }
        }

        // store w tile: sW[o][j], stride 68, STS.128
        #pragma unroll
        for (int s=0;s<4;s++){
            int q = t + s*256;
            int o = q >> 4, j4 = (q & 15) << 2;
            *(float4*)(sW + o*WST + j4) = wreg[s];
        }
        __syncthreads();

        // FMA phase: rank-64 update; per jq handle 4 j via LDS.128 (= 2 f32x2)
        const float* zb = sZ + bF*ZST;
        #pragma unroll 4
        for (int jq=0;jq<16;jq++){
            ulonglong2 wv[4], zv[D3];
            #pragma unroll
            for (int oo=0;oo<4;oo++)
                wv[oo] = *(const ulonglong2*)(sW + (og+16*oo)*WST + 4*jq);
            #pragma unroll
            for (int k=0;k<D3;k++)
                zv[k] = *(const ulonglong2*)(zb + (k<<4)*ZST + 4*jq);
            #pragma unroll
            for (int oo=0;oo<4;oo++)
                #pragma unroll
                for (int k=0;k<D3;k++){
                    ffma2(acc2[oo][k], wv[oo].x, zv[k].x);
                    ffma2(acc2[oo][k], wv[oo].y, zv[k].y);
                }
        }
    }

    if (B0+bF < n){
        float* ob = out + (size_t)(B0+bF)*576 + K0;
        #pragma unroll
        for (int oo=0;oo<4;oo++){
            int o = og + 16*oo;
            #pragma unroll
            for (int k=0;k<D3;k++){
                unsigned long long v = acc2[oo][k];
                float lo = __uint_as_float((unsigned int)v);
                float hi = __uint_as_float((unsigned int)(v >> 32));
                ob[o*9 + k] += lo + hi;
            }
        }
    }
}

// ---------------------------------------------------------------------------
// launch — operand identification is SIZE-BASED (metadata order interleaves
// x1_l0, x2_l0, x1_l1, x2_l1, x1_l2, x2_l2, weight).
// ---------------------------------------------------------------------------
extern "C" void kernel_launch(void* const* d_in, const int* in_sizes, int n_in,
                              void* d_out, int out_size){
    const long long WELEMS = (long long)NPATH * 64 * 64 * 64;  // 2,883,584

    const float* w = nullptr;
    long long minOther = 0x7fffffffffffLL;
    for (int i = 0; i < n_in; i++){
        if ((long long)in_sizes[i] == WELEMS && w == nullptr) { w = (const float*)d_in[i]; }
    }
    for (int i = 0; i < n_in; i++){
        if ((const float*)d_in[i] == w) continue;
        if ((long long)in_sizes[i] < minOther) minOther = in_sizes[i];
    }
    const int nvec = (int)(minOther / 64);   // N  (l0 input is N*64*1)

    const float* x1p[3] = {nullptr,nullptr,nullptr};
    const float* x2p[3] = {nullptr,nullptr,nullptr};
    for (int i = 0; i < n_in; i++){
        const float* ptr = (const float*)d_in[i];
        if (ptr == w) continue;
        long long sz = in_sizes[i];
        for (int l = 0; l < 3; l++){
            if (sz == (long long)nvec * 64 * (2*l+1)){
                if (!x1p[l]) x1p[l] = ptr; else x2p[l] = ptr;
                break;
            }
        }
    }

    float* out = (float*)d_out;
    const int nb = (nvec + 15) / 16;

    hctp_build_cg<<<1, 32>>>();
    hctp_zero<<<1024, 256>>>(out, (size_t)nvec*576);

#define LAUNCH_PATH(Pp,L1,L2,L3) do { \
    constexpr int smem = tp_smem_floats(L1,L2,L3) * 4; \
    cudaFuncSetAttribute(tp_kernel<L1,L2,L3,Pp>, cudaFuncAttributeMaxDynamicSharedMemorySize, smem); \
    tp_kernel<L1,L2,L3,Pp><<<nb, 256, smem>>>(x1p[L1], x2p[L2], w, out, nvec); \
} while(0)

    LAUNCH_PATH(0, 0,0,0);
    LAUNCH_PATH(1, 0,1,1);
    LAUNCH_PATH(2, 0,2,2);
    LAUNCH_PATH(3, 1,0,1);
    LAUNCH_PATH(4, 1,1,0);
    LAUNCH_PATH(5, 1,1,2);
    LAUNCH_PATH(6, 1,2,1);
    LAUNCH_PATH(7, 2,0,2);
    LAUNCH_PATH(8, 2,1,1);
    LAUNCH_PATH(9, 2,2,0);
    LAUNCH_PATH(10,2,2,2);
#undef LAUNCH_PATH
}